// round 9
// baseline (speedup 1.0000x reference)
#include <cuda_runtime.h>
#include <math.h>
#include <cstdint>
#include <float.h>

#define NB_MAX   256
#define THREADS  512
#define NWARP    16
#define NBIN     512
#define BINSCALE 64.0f        // bin = r * 64, covers r in [0, 8)
#define MAXM     16384
#define MAXP     32768

// -------- device scratch (static; no allocations) --------
__device__ float4 g_ms[MAXM];            // norm-sorted model (x,y,z,b=|g|^2)
__device__ float4 g_pu[MAXP];            // unsorted pred (qx,qy,qz,a)
__device__ float2 g_pu2[MAXP];           // unsorted pred (w, r)
__device__ float4 g_ps[MAXP];            // sorted pred
__device__ float2 g_ps2[MAXP];
__device__ int g_mhist[NBIN], g_phist[NBIN];
__device__ int g_mstart[NBIN + 1], g_pstart[NBIN + 1];
__device__ int g_mcur[NBIN], g_pcur[NBIN];
__device__ float g_partials[NB_MAX];
__device__ unsigned int g_bar1, g_bar2, g_bar3, g_ticket;  // zero-init; reset at end

__device__ __forceinline__ int norm_bin(float r) {
    int b = (int)(r * BINSCALE);
    if (b < 0) b = 0;
    if (b > NBIN - 1) b = NBIN - 1;
    return b;
}

__device__ __forceinline__ void grid_bar(unsigned int* ctr, unsigned int tgt) {
    __syncthreads();
    if (threadIdx.x == 0) {
        __threadfence();
        atomicAdd(ctr, 1u);
        while (*((volatile unsigned int*)ctr) < tgt) { __nanosleep(64); }
        __threadfence();
    }
    __syncthreads();
}

// Pack rows [row0, row0+n) of g_ms into pair-interleaved smem records
// [x0,x1,y0,y1,z0,z1,w0,w1]; pad odd tail with a huge-w dummy.
__device__ __forceinline__ void pack_rows(float* s_model, int row0, int n, int tid) {
    for (int e = tid; e < n; e += THREADS) {
        float4 gm = g_ms[row0 + e];
        int p = e >> 1, o = e & 1;
        s_model[p * 8 + 0 + o] = gm.x;
        s_model[p * 8 + 2 + o] = gm.y;
        s_model[p * 8 + 4 + o] = gm.z;
        s_model[p * 8 + 6 + o] = gm.w;
    }
    if ((n & 1) && tid == 0) {
        int p = n >> 1;
        s_model[p * 8 + 1] = 0.f; s_model[p * 8 + 3] = 0.f;
        s_model[p * 8 + 5] = 0.f; s_model[p * 8 + 7] = 3.0e37f;
    }
}

// Packed f32x2 min-scan over npairs records; warp-sliced; accumulates into m_lo/m_hi.
__device__ __forceinline__ void scan_pairs(const float* s_model, int npairs, int warp,
                                           const uint64_t* qx2, const uint64_t* qy2,
                                           const uint64_t* qz2, float* m_lo, float* m_hi) {
    int ps = (npairs + NWARP - 1) / NWARP;
    int pb = warp * ps; if (pb > npairs) pb = npairs;
    int pe = pb + ps;   if (pe > npairs) pe = npairs;
    uint32_t addr;
    {
        uint64_t a64;
        asm("cvta.to.shared.u64 %0, %1;" : "=l"(a64) : "l"(s_model + (size_t)pb * 8));
        addr = (uint32_t)a64;
    }
    #pragma unroll 4
    for (int p = pb; p < pe; ++p, addr += 32u) {
        uint64_t x2, y2, z2, w2;
        asm("ld.shared.v2.u64 {%0,%1}, [%2];"    : "=l"(x2), "=l"(y2) : "r"(addr));
        asm("ld.shared.v2.u64 {%0,%1}, [%2+16];" : "=l"(z2), "=l"(w2) : "r"(addr));
        #pragma unroll
        for (int k = 0; k < 4; k++) {
            uint64_t d2;
            asm("fma.rn.f32x2 %0, %1, %2, %3;" : "=l"(d2) : "l"(qz2[k]), "l"(z2), "l"(w2));
            asm("fma.rn.f32x2 %0, %1, %2, %0;" : "+l"(d2) : "l"(qy2[k]), "l"(y2));
            asm("fma.rn.f32x2 %0, %1, %2, %0;" : "+l"(d2) : "l"(qx2[k]), "l"(x2));
            float dlo, dhi;
            asm("mov.b64 {%0,%1}, %2;" : "=f"(dlo), "=f"(dhi) : "l"(d2));
            m_lo[k] = fminf(m_lo[k], dlo);
            m_hi[k] = fminf(m_hi[k], dhi);
        }
    }
}

__global__ __launch_bounds__(THREADS, 1)
void cd_kernel(const float* __restrict__ vis,
               const float* __restrict__ tac,
               const float* __restrict__ model,
               const float* __restrict__ scale,
               const float* __restrict__ state,
               float* __restrict__ out,
               int nv, int nt, int nm,
               float wv, float wt, int nbp) {
    extern __shared__ float s_model[];          // up to nm pairs (131072 B)
    __shared__ float s_par[13];
    __shared__ float s_min[NWARP * 128];
    __shared__ float s_m1[128];
    __shared__ int s_scan[NBIN];
    __shared__ int s_mstart[NBIN + 1];
    __shared__ int s_wlo_i, s_whi_i, s_slab0, s_np1, s_r0, s_r1, s_skip, s_last;

    const int tid  = threadIdx.x;
    const int lane = tid & 31;
    const int warp = tid >> 5;
    const int ntot = nv + nt;
    const unsigned int GRID = gridDim.x;
    const int gstride = (int)GRID * THREADS;
    const int gtid = blockIdx.x * THREADS + tid;

    // ---- params (every CTA computes its own copy) ----
    if (tid == 0) {
        float ox = state[3], oy = state[4], oz = state[5];
        float sx = sinf(ox), cx = cosf(ox);
        float sy = sinf(oy), cy = cosf(oy);
        float sz = sinf(oz), cz = cosf(oz);
        s_par[0] = cz * cy;
        s_par[1] = cz * sy * sx - sz * cx;
        s_par[2] = cz * sy * cx + sz * sx;
        s_par[3] = sz * cy;
        s_par[4] = sz * sy * sx + cz * cx;
        s_par[5] = sz * sy * cx - cz * sx;
        s_par[6] = -sy;
        s_par[7] = cy * sx;
        s_par[8] = cy * cx;
        s_par[9]  = state[0];
        s_par[10] = state[1];
        s_par[11] = state[2];
        s_par[12] = 1.0f / scale[0];
    }
    __syncthreads();

    // ================= Phase A: histograms + pred transform =================
    for (int j = gtid; j < nm && j < MAXM; j += gstride) {
        float gx = model[3 * j], gy = model[3 * j + 1], gz = model[3 * j + 2];
        float b = fmaf(gx, gx, fmaf(gy, gy, gz * gz));
        atomicAdd(&g_mhist[norm_bin(sqrtf(b))], 1);
    }
    for (int i = gtid; i < ntot && i < MAXP; i += gstride) {
        const float* src; int idx; float w;
        if (i < nv) { src = vis; idx = i;      w = wv; }
        else        { src = tac; idx = i - nv; w = wt; }
        float vx = src[3 * idx + 0] - s_par[9];
        float vy = src[3 * idx + 1] - s_par[10];
        float vz = src[3 * idx + 2] - s_par[11];
        float inv_s = s_par[12];
        float px = (vx * s_par[0] + vy * s_par[3] + vz * s_par[6]) * inv_s;
        float py = (vx * s_par[1] + vy * s_par[4] + vz * s_par[7]) * inv_s;
        float pz = (vx * s_par[2] + vy * s_par[5] + vz * s_par[8]) * inv_s;
        float a = fmaf(px, px, fmaf(py, py, pz * pz));
        float r = sqrtf(a);
        g_pu[i]  = make_float4(-2.0f * px, -2.0f * py, -2.0f * pz, a);
        g_pu2[i] = make_float2(w, r);
        atomicAdd(&g_phist[norm_bin(r)], 1);
    }
    grid_bar(&g_bar1, GRID);

    // ================= Phase B: CTA 0 prefix sums =================
    if (blockIdx.x == 0) {
        int v = g_mhist[tid];
        s_scan[tid] = v; __syncthreads();
        for (int off = 1; off < NBIN; off <<= 1) {
            int t = (tid >= off) ? s_scan[tid - off] : 0;
            __syncthreads(); s_scan[tid] += t; __syncthreads();
        }
        g_mstart[tid] = s_scan[tid] - v;
        g_mcur[tid]   = s_scan[tid] - v;
        if (tid == NBIN - 1) g_mstart[NBIN] = s_scan[tid];
        g_mhist[tid] = 0;
        __syncthreads();
        int v2 = g_phist[tid];
        s_scan[tid] = v2; __syncthreads();
        for (int off = 1; off < NBIN; off <<= 1) {
            int t = (tid >= off) ? s_scan[tid - off] : 0;
            __syncthreads(); s_scan[tid] += t; __syncthreads();
        }
        g_pstart[tid] = s_scan[tid] - v2;
        g_pcur[tid]   = s_scan[tid] - v2;
        if (tid == NBIN - 1) g_pstart[NBIN] = s_scan[tid];
        g_phist[tid] = 0;
        __threadfence();
    }
    grid_bar(&g_bar2, GRID);

    // ================= Phase C: scatter into norm order =================
    for (int j = gtid; j < nm && j < MAXM; j += gstride) {
        float gx = model[3 * j], gy = model[3 * j + 1], gz = model[3 * j + 2];
        float b = fmaf(gx, gx, fmaf(gy, gy, gz * gz));
        int pos = atomicAdd(&g_mcur[norm_bin(sqrtf(b))], 1);
        g_ms[pos] = make_float4(gx, gy, gz, b);
    }
    for (int i = gtid; i < ntot && i < MAXP; i += gstride) {
        float4 P = g_pu[i]; float2 P2 = g_pu2[i];
        int pos = atomicAdd(&g_pcur[norm_bin(P2.y)], 1);
        g_ps[pos] = P; g_ps2[pos] = P2;
    }
    grid_bar(&g_bar3, GRID);

    // stage bin-start table
    for (int j = tid; j <= NBIN; j += THREADS) s_mstart[j] = g_mstart[j];
    __syncthreads();

    // ================= Phase D: pruned chamfer per pred-block =================
    for (int pb = blockIdx.x; pb < nbp; pb += (int)GRID) {
        // load 4 sorted preds per lane
        float a[4], wgt[4];
        uint64_t qx2[4], qy2[4], qz2[4];
        #pragma unroll
        for (int k = 0; k < 4; k++) {
            int i = pb * 128 + k * 32 + lane;
            float qx = 0.f, qy = 0.f, qz = 0.f;
            a[k] = 0.f; wgt[k] = 0.f;
            if (i < ntot) {
                float4 P = g_ps[i]; float2 P2 = g_ps2[i];
                qx = P.x; qy = P.y; qz = P.z; a[k] = P.w; wgt[k] = P2.x;
            }
            asm("mov.b64 %0, {%1,%1};" : "=l"(qx2[k]) : "f"(qx));
            asm("mov.b64 %0, {%1,%1};" : "=l"(qy2[k]) : "f"(qy));
            asm("mov.b64 %0, {%1,%1};" : "=l"(qz2[k]) : "f"(qz));
        }

        if (tid == 0) {
            s_wlo_i = 0x7f7fffff;   // +FLT_MAX
            s_whi_i = 0;            // +0.0
            int imid = pb * 128 + 64; if (imid >= ntot) imid = ntot - 1;
            float rmid = g_ps2[imid].y;
            int mrow = s_mstart[norm_bin(rmid)];
            int np1 = nm < 512 ? nm : 512;
            int slab0 = mrow - np1 / 2;
            if (slab0 < 0) slab0 = 0;
            if (slab0 > nm - np1) slab0 = nm - np1;
            s_slab0 = slab0; s_np1 = np1;
        }
        __syncthreads();

        // ---- stage 1: slab scan for upper bound ----
        pack_rows(s_model, s_slab0, s_np1, tid);
        __syncthreads();
        {
            float m_lo[4], m_hi[4];
            #pragma unroll
            for (int k = 0; k < 4; k++) { m_lo[k] = FLT_MAX; m_hi[k] = FLT_MAX; }
            scan_pairs(s_model, (s_np1 + 1) >> 1, warp, qx2, qy2, qz2, m_lo, m_hi);
            #pragma unroll
            for (int k = 0; k < 4; k++)
                s_min[warp * 128 + k * 32 + lane] = fminf(m_lo[k], m_hi[k]);
        }
        __syncthreads();
        if (warp == 0) {
            #pragma unroll
            for (int k = 0; k < 4; k++) {
                int pidx = k * 32 + lane;
                float m = s_min[pidx];
                #pragma unroll
                for (int s = 1; s < NWARP; s++) m = fminf(m, s_min[s * 128 + pidx]);
                s_m1[pidx] = m;
                int i = pb * 128 + pidx;
                if (i < ntot) {
                    float r = g_ps2[i].y;
                    float W = sqrtf(fmaxf(a[k] + m, 0.f)) * 1.002f + 1e-5f;
                    float wlo = fmaxf(r - W, 0.f);
                    float whi = r + W;
                    atomicMin(&s_wlo_i, __float_as_int(wlo));
                    atomicMax(&s_whi_i, __float_as_int(whi));
                }
            }
        }
        __syncthreads();
        if (tid == 0) {
            float wlo = __int_as_float(s_wlo_i);
            float whi = __int_as_float(s_whi_i);
            int r0 = s_mstart[norm_bin(wlo)];
            int r1 = s_mstart[norm_bin(whi) + 1];
            s_r0 = r0; s_r1 = r1;
            s_skip = (r0 >= s_slab0 && r1 <= s_slab0 + s_np1) ? 1 : 0;
        }
        __syncthreads();

        // ---- stage 2: window scan (seeded with slab mins) ----
        if (!s_skip) {
            int r0 = s_r0, np2 = s_r1 - s_r0;
            pack_rows(s_model, r0, np2, tid);
            __syncthreads();
            float m_lo[4], m_hi[4];
            #pragma unroll
            for (int k = 0; k < 4; k++) {
                m_lo[k] = s_m1[k * 32 + lane];
                m_hi[k] = FLT_MAX;
            }
            scan_pairs(s_model, (np2 + 1) >> 1, warp, qx2, qy2, qz2, m_lo, m_hi);
            #pragma unroll
            for (int k = 0; k < 4; k++)
                s_min[warp * 128 + k * 32 + lane] = fminf(m_lo[k], m_hi[k]);
            __syncthreads();
            if (warp == 0) {
                #pragma unroll
                for (int k = 0; k < 4; k++) {
                    int pidx = k * 32 + lane;
                    float m = s_min[pidx];
                    #pragma unroll
                    for (int s = 1; s < NWARP; s++) m = fminf(m, s_min[s * 128 + pidx]);
                    s_m1[pidx] = m;
                }
            }
            __syncthreads();
        }

        // ---- block-weighted sum ----
        if (warp == 0) {
            float vsum = 0.0f;
            #pragma unroll
            for (int k = 0; k < 4; k++) {
                int pidx = k * 32 + lane;
                int i = pb * 128 + pidx;
                if (i < ntot) vsum += (a[k] + s_m1[pidx]) * wgt[k];
            }
            #pragma unroll
            for (int o = 16; o > 0; o >>= 1)
                vsum += __shfl_down_sync(0xffffffffu, vsum, o);
            if (lane == 0 && pb < NB_MAX) g_partials[pb] = vsum;
        }
        __syncthreads();
    }

    // ================= final fixed-order reduction =================
    if (tid == 0) {
        __threadfence();
        unsigned int t = atomicAdd(&g_ticket, 1u);
        s_last = (t == GRID - 1u) ? 1 : 0;
    }
    __syncthreads();
    if (s_last && warp == 0) {
        float s = 0.0f;
        for (int b = lane; b < nbp; b += 32)
            s += *((volatile float*)&g_partials[b]);
        #pragma unroll
        for (int o = 16; o > 0; o >>= 1)
            s += __shfl_down_sync(0xffffffffu, s, o);
        if (lane == 0) {
            out[0] = s;
            g_ticket = 0; g_bar1 = 0; g_bar2 = 0; g_bar3 = 0;  // reset for replay
        }
    }
}

extern "C" void kernel_launch(void* const* d_in, const int* in_sizes, int n_in,
                              void* d_out, int out_size) {
    const float* vis   = (const float*)d_in[0];  // visual_points  (16384,3)
    const float* tac   = (const float*)d_in[1];  // tactile_points (2048,3)
    const float* model = (const float*)d_in[2];  // model_points   (8192,3)
    const float* scale = (const float*)d_in[3];  // scalar
    const float* state = (const float*)d_in[4];  // (6,)
    float* out = (float*)d_out;

    int nv = in_sizes[0] / 3;
    int nt = in_sizes[1] / 3;
    int nm = in_sizes[2] / 3;

    int ntot = nv + nt;
    int nbp = (ntot + 127) / 128;               // 144 for default shapes
    if (nbp > NB_MAX) nbp = NB_MAX;

    int grid = nbp < 148 ? nbp : 148;           // all-resident (1 CTA/SM) for barriers

    int nm_pairs = (nm + 1) / 2;
    size_t smem = (size_t)nm_pairs * 32;        // worst-case window = full model
    cudaFuncSetAttribute(cd_kernel, cudaFuncAttributeMaxDynamicSharedMemorySize,
                         (int)smem);

    float wv = 1.0f / (float)nv;
    float wt = 0.1f / (float)nt;

    cd_kernel<<<grid, THREADS, smem>>>(vis, tac, model, scale, state, out,
                                       nv, nt, nm, wv, wt, nbp);
}